// round 1
// baseline (speedup 1.0000x reference)
#include <cuda_runtime.h>

#define BB  2048
#define IN  512
#define NF  256
#define NP  256
#define EPS 1e-8f

// Intermediates (allocation-free rule: device globals)
__device__ float g_xsigT[NF * BB];   // [f][b]  sigmoid(x @ W^T), f-major
__device__ float g_psigT[NF * NP];   // [f][p]  sigmoid(prototypes), f-major

__device__ __forceinline__ float sigmoidf(float v) {
    return 1.0f / (1.0f + __expf(-v));
}

// ---------------------------------------------------------------------------
// Kernel A: prototypes (NP x NF) -> sigmoid -> transposed g_psigT [f][p]
// Tiny (64K elems); simplicity over bandwidth.
// ---------------------------------------------------------------------------
__global__ void proto_sig_kernel(const float* __restrict__ prototypes) {
    int p = blockIdx.x;
    int f = threadIdx.x;
    g_psigT[f * NP + p] = sigmoidf(prototypes[p * NF + f]);
}

// ---------------------------------------------------------------------------
// Kernel B: x (B x IN) @ features^T (NF x IN), sigmoid, store g_xsigT [f][b].
// 64(b) x 64(f) tile, 256 threads, 4x4 per thread, K-chunks of 16.
// Grid (32, 4) = 128 CTAs.
// ---------------------------------------------------------------------------
__global__ void feat_gemm_kernel(const float* __restrict__ x,
                                 const float* __restrict__ features) {
    __shared__ float xs[16][64];   // [k][b]
    __shared__ float ws[16][64];   // [k][f]

    const int tid = threadIdx.x;
    const int tx = tid & 15;       // f direction (x4)
    const int ty = tid >> 4;       // b direction (x4)
    const int b0 = blockIdx.x * 64;
    const int f0 = blockIdx.y * 64;

    // loader mapping: 256 threads load 64 rows x 16 k (1 float4 each)
    const int lrow = tid >> 2;     // 0..63
    const int lkv  = tid & 3;      // 0..3 (float4 index along k)

    float acc[4][4] = {};

    for (int k0 = 0; k0 < IN; k0 += 16) {
        float4 xv = *(const float4*)&x[(b0 + lrow) * IN + k0 + lkv * 4];
        float4 wv = *(const float4*)&features[(f0 + lrow) * IN + k0 + lkv * 4];
        xs[lkv * 4 + 0][lrow] = xv.x;
        xs[lkv * 4 + 1][lrow] = xv.y;
        xs[lkv * 4 + 2][lrow] = xv.z;
        xs[lkv * 4 + 3][lrow] = xv.w;
        ws[lkv * 4 + 0][lrow] = wv.x;
        ws[lkv * 4 + 1][lrow] = wv.y;
        ws[lkv * 4 + 2][lrow] = wv.z;
        ws[lkv * 4 + 3][lrow] = wv.w;
        __syncthreads();

        #pragma unroll
        for (int k = 0; k < 16; k++) {
            float4 a = *(const float4*)&xs[k][ty * 4];
            float4 w = *(const float4*)&ws[k][tx * 4];
            float av[4] = {a.x, a.y, a.z, a.w};
            float wv4[4] = {w.x, w.y, w.z, w.w};
            #pragma unroll
            for (int i = 0; i < 4; i++)
                #pragma unroll
                for (int j = 0; j < 4; j++)
                    acc[i][j] = fmaf(av[i], wv4[j], acc[i][j]);
        }
        __syncthreads();
    }

    // Epilogue: sigmoid, store transposed: x_sigT[f][b], float4 along b
    #pragma unroll
    for (int j = 0; j < 4; j++) {
        int f = f0 + tx * 4 + j;
        float4 o;
        o.x = sigmoidf(acc[0][j]);
        o.y = sigmoidf(acc[1][j]);
        o.z = sigmoidf(acc[2][j]);
        o.w = sigmoidf(acc[3][j]);
        *(float4*)&g_xsigT[f * BB + b0 + ty * 4] = o;
    }
}

// ---------------------------------------------------------------------------
// Kernel C: Tversky core.
// I[b,p] = sum_f min(xs, ps);  x_diff = Sx[b]-I;  p_diff = Sp[p]-I.
// out = I / (I + a*(Sx-I) + b*(Sp-I) + eps) + bias[p]
// 64(b) x 64(p) tile, 256 threads, 4x4 per thread, f-chunks of 32.
// Grid (32, 4) = 128 CTAs.
// ---------------------------------------------------------------------------
__global__ void tversky_kernel(const float* __restrict__ bias,
                               const float* __restrict__ alphap,
                               const float* __restrict__ betap,
                               float* __restrict__ out) {
    __shared__ float xs[32][64];   // [f][b]
    __shared__ float ps[32][64];   // [f][p]
    __shared__ float sxs[64];
    __shared__ float sps[64];

    const int tid = threadIdx.x;
    const int tx = tid & 15;       // p direction (x4)
    const int ty = tid >> 4;       // b direction (x4)
    const int b0 = blockIdx.x * 64;
    const int p0 = blockIdx.y * 64;

    float acc[4][4] = {};
    float sx[4] = {};
    float sp[4] = {};

    for (int f0 = 0; f0 < NF; f0 += 32) {
        // load 32 x 64 floats per operand: 512 float4, 2 per thread
        #pragma unroll
        for (int i = 0; i < 2; i++) {
            int idx = tid + i * 256;        // float4 index 0..511
            int fr  = idx >> 4;             // 16 float4 per row
            int bc  = (idx & 15) * 4;
            *(float4*)&xs[fr][bc] = *(const float4*)&g_xsigT[(f0 + fr) * BB + b0 + bc];
            *(float4*)&ps[fr][bc] = *(const float4*)&g_psigT[(f0 + fr) * NP + p0 + bc];
        }
        __syncthreads();

        #pragma unroll 8
        for (int k = 0; k < 32; k++) {
            float4 a = *(const float4*)&xs[k][ty * 4];
            float4 p = *(const float4*)&ps[k][tx * 4];
            float av[4] = {a.x, a.y, a.z, a.w};
            float pv[4] = {p.x, p.y, p.z, p.w};
            #pragma unroll
            for (int i = 0; i < 4; i++)
                #pragma unroll
                for (int j = 0; j < 4; j++)
                    acc[i][j] += fminf(av[i], pv[j]);
            if (tx == 0) {
                #pragma unroll
                for (int i = 0; i < 4; i++) sx[i] += av[i];
            }
            if (ty == 0) {
                #pragma unroll
                for (int j = 0; j < 4; j++) sp[j] += pv[j];
            }
        }
        __syncthreads();
    }

    // Broadcast row/col sums
    if (tx == 0) {
        #pragma unroll
        for (int i = 0; i < 4; i++) sxs[ty * 4 + i] = sx[i];
    }
    if (ty == 0) {
        #pragma unroll
        for (int j = 0; j < 4; j++) sps[tx * 4 + j] = sp[j];
    }
    __syncthreads();

    const float alpha = *alphap;
    const float beta  = *betap;

    float bi[4], spv[4];
    #pragma unroll
    for (int j = 0; j < 4; j++) {
        bi[j]  = bias[p0 + tx * 4 + j];
        spv[j] = sps[tx * 4 + j];
    }

    #pragma unroll
    for (int i = 0; i < 4; i++) {
        int b = b0 + ty * 4 + i;
        float Sx = sxs[ty * 4 + i];
        float4 o;
        float r[4];
        #pragma unroll
        for (int j = 0; j < 4; j++) {
            float I = acc[i][j];
            float denom = I + alpha * (Sx - I) + beta * (spv[j] - I) + EPS;
            r[j] = I / denom + bi[j];
        }
        o.x = r[0]; o.y = r[1]; o.z = r[2]; o.w = r[3];
        *(float4*)&out[b * NP + p0 + tx * 4] = o;
    }
}

// ---------------------------------------------------------------------------
// Launch. Inputs: x, features, prototypes, bias, alpha, beta (metadata order).
// ---------------------------------------------------------------------------
extern "C" void kernel_launch(void* const* d_in, const int* in_sizes, int n_in,
                              void* d_out, int out_size) {
    const float* x          = (const float*)d_in[0];
    const float* features   = (const float*)d_in[1];
    const float* prototypes = (const float*)d_in[2];
    const float* bias       = (const float*)d_in[3];
    const float* alpha      = (const float*)d_in[4];
    const float* beta       = (const float*)d_in[5];
    float* out = (float*)d_out;

    proto_sig_kernel<<<NP, NF>>>(prototypes);
    feat_gemm_kernel<<<dim3(BB / 64, NF / 64), 256>>>(x, features);
    tversky_kernel<<<dim3(BB / 64, NP / 64), 256>>>(bias, alpha, beta, out);
}

// round 5
// speedup vs baseline: 1.3505x; 1.3505x over previous
#include <cuda_runtime.h>
#include <cstdint>

#define BB  2048
#define IN  512
#define NF  256
#define NP  256
#define EPS 1e-8f

// ---------------------------------------------------------------------------
// Device globals (allocation-free rule)
// ---------------------------------------------------------------------------
__device__ float g_xsigT[NF * BB];     // [f][b] sigmoid(x @ W^T), f-major
__device__ float g_psigT[NF * NP];     // [f][p] sigmoid(prototypes), f-major
__device__ float g_SxP[4 * BB];        // partial row sums of x_sig (per f-tile)
__device__ float g_SpP[2 * NP];        // partial row sums of p_sig (per f-half)

__device__ __forceinline__ float sigmoidf(float v) {
    return 1.0f / (1.0f + __expf(-v));
}

__device__ __forceinline__ uint32_t smem_u32(const void* p) {
    uint32_t a;
    asm("{ .reg .u64 t; cvta.to.shared.u64 t, %1; cvt.u32.u64 %0, t; }"
        : "=r"(a) : "l"(p));
    return a;
}

__device__ __forceinline__ uint32_t tf32r(float v) {
    uint32_t u;
    asm("cvt.rna.tf32.f32 %0, %1;" : "=r"(u) : "f"(v));
    return u;
}

__device__ __forceinline__ void ldsm_x4(uint32_t& r0, uint32_t& r1,
                                        uint32_t& r2, uint32_t& r3, uint32_t addr) {
    asm volatile("ldmatrix.sync.aligned.m8n8.x4.shared.b16 {%0,%1,%2,%3}, [%4];"
                 : "=r"(r0), "=r"(r1), "=r"(r2), "=r"(r3) : "r"(addr));
}

__device__ __forceinline__ void mma_tf32(float* d, const uint32_t* a, const uint32_t* b) {
    asm volatile(
        "mma.sync.aligned.m16n8k8.row.col.f32.tf32.tf32.f32 "
        "{%0,%1,%2,%3}, {%4,%5,%6,%7}, {%8,%9}, {%0,%1,%2,%3};"
        : "+f"(d[0]), "+f"(d[1]), "+f"(d[2]), "+f"(d[3])
        : "r"(a[0]), "r"(a[1]), "r"(a[2]), "r"(a[3]), "r"(b[0]), "r"(b[1]));
}

// ---------------------------------------------------------------------------
// Kernel A: prototypes (NP x NF) -> sigmoid -> g_psigT [f][p] + Sp partials.
// grid (8, 2): 32 p x 128 f per CTA.  block (32, 8).
// ---------------------------------------------------------------------------
__global__ void proto_sig_kernel(const float* __restrict__ prototypes) {
    __shared__ float t[32][131];        // [p][f], stride 131 (3-bank shift/row)
    const int tx = threadIdx.x, ty = threadIdx.y;
    const int p0 = blockIdx.x * 32, f0 = blockIdx.y * 128;

    #pragma unroll
    for (int i = 0; i < 4; i++) {
        int p = i * 8 + ty;
        #pragma unroll
        for (int c = 0; c < 4; c++)
            t[p][c * 32 + tx] = sigmoidf(prototypes[(p0 + p) * NF + f0 + c * 32 + tx]);
    }
    __syncthreads();

    #pragma unroll
    for (int i = 0; i < 16; i++) {
        int f = ty * 16 + i;
        g_psigT[(f0 + f) * NP + p0 + tx] = t[tx][f];
    }

    if (ty == 0) {
        float s = 0.f;
        #pragma unroll 16
        for (int f = 0; f < 128; f++) s += t[tx][f];
        g_SpP[blockIdx.y * NP + p0 + tx] = s;
    }
}

// ---------------------------------------------------------------------------
// Kernel B: tensor-core tf32 GEMM via mma.sync.
// x (B x IN) @ features^T (NF x IN) -> sigmoid -> g_xsigT [f][b] + Sx partials.
// CTA tile 64(b) x 64(f), 128 threads (4 warps, 32x32 warp tiles).
// K chunks of 32, double-buffered smem.  grid (32, 4) = 128 CTAs.
// ---------------------------------------------------------------------------
#define KC      32
#define ASTR    36                      // smem row stride in floats (144B)
#define TILE_FL (64 * ASTR)             // floats per buffer

__global__ void __launch_bounds__(128, 1)
feat_gemm_kernel(const float* __restrict__ x,
                 const float* __restrict__ features) {
    __shared__ __align__(16) float As[2][TILE_FL];
    __shared__ __align__(16) float Bs[2][TILE_FL];

    const int tid  = threadIdx.x;
    const int wid  = tid >> 5;
    const int lane = tid & 31;
    const int b0 = blockIdx.x * 64;
    const int f0 = blockIdx.y * 64;
    const int m_off = (wid & 1) * 32;
    const int n_off = (wid >> 1) * 32;

    // global loader mapping: 512 float4 per tile, 4 per thread
    int lrow[4], lkq[4];
    #pragma unroll
    for (int i = 0; i < 4; i++) {
        int idx = tid + i * 128;
        lrow[i] = idx >> 3;             // 0..63
        lkq[i]  = idx & 7;              // float4 slot along k
    }

    // ldmatrix per-thread byte offsets
    const uint32_t sA = smem_u32(As);
    const uint32_t sB = smem_u32(Bs);
    const uint32_t a_off = (uint32_t)(((lane & 15) + m_off) * ASTR + ((lane >> 4) & 1) * 4) * 4;
    const uint32_t b_off = (uint32_t)((((lane & 7) + ((lane >> 4) & 1) * 8) + n_off) * ASTR
                                      + ((lane >> 3) & 1) * 4) * 4;

    float4 av[4], bv[4];
    #pragma unroll
    for (int i = 0; i < 4; i++) {
        av[i] = *(const float4*)&x[(size_t)(b0 + lrow[i]) * IN + lkq[i] * 4];
        bv[i] = *(const float4*)&features[(size_t)(f0 + lrow[i]) * IN + lkq[i] * 4];
    }

    float acc[2][4][4] = {};            // [mt][n-tile][4]

    for (int c = 0; c < IN / KC; c++) {
        const int buf = c & 1;

        #pragma unroll
        for (int i = 0; i < 4; i++) {
            uint4 ua = make_uint4(tf32r(av[i].x), tf32r(av[i].y), tf32r(av[i].z), tf32r(av[i].w));
            uint4 ub = make_uint4(tf32r(bv[i].x), tf32r(bv[i].y), tf32r(bv[i].z), tf32r(bv[i].w));
            *(uint4*)&As[buf][lrow[i] * ASTR + lkq[i] * 4] = ua;
            *(uint4*)&Bs[buf][lrow[i] * ASTR + lkq[i] * 4] = ub;
        }
        __syncthreads();

        if (c + 1 < IN / KC) {
            const int k0 = (c + 1) * KC;
            #pragma unroll
            for (int i = 0; i < 4; i++) {
                av[i] = *(const float4*)&x[(size_t)(b0 + lrow[i]) * IN + k0 + lkq[i] * 4];
                bv[i] = *(const float4*)&features[(size_t)(f0 + lrow[i]) * IN + k0 + lkq[i] * 4];
            }
        }

        const uint32_t baseA = sA + (uint32_t)buf * TILE_FL * 4;
        const uint32_t baseB = sB + (uint32_t)buf * TILE_FL * 4;

        #pragma unroll
        for (int s = 0; s < 4; s++) {
            const uint32_t kb = (uint32_t)(s * 8) * 4;
            uint32_t aa[2][4], bb[2][4];
            ldsm_x4(aa[0][0], aa[0][1], aa[0][2], aa[0][3], baseA + a_off + kb);
            ldsm_x4(aa[1][0], aa[1][1], aa[1][2], aa[1][3], baseA + a_off + kb + 16 * ASTR * 4);
            ldsm_x4(bb[0][0], bb[0][1], bb[0][2], bb[0][3], baseB + b_off + kb);
            ldsm_x4(bb[1][0], bb[1][1], bb[1][2], bb[1][3], baseB + b_off + kb + 16 * ASTR * 4);
            #pragma unroll
            for (int mt = 0; mt < 2; mt++)
                #pragma unroll
                for (int nt = 0; nt < 4; nt++)
                    mma_tf32(acc[mt][nt], aa[mt], &bb[nt >> 1][(nt & 1) * 2]);
        }
        __syncthreads();
    }

    // ---- epilogue: sigmoid, transpose-stage through smem, coalesced store ----
    float* Csm = &As[0][0];             // 64 x 68 overlay (4352 floats: fits in As)
    #define CSTR 68
    __syncthreads();

    {
        const int mrow = m_off + (lane >> 2);
        const int ncol = n_off + 2 * (lane & 3);
        #pragma unroll
        for (int mt = 0; mt < 2; mt++) {
            #pragma unroll
            for (int nt = 0; nt < 4; nt++) {
                const int m = mrow + mt * 16;
                const int n = ncol + nt * 8;
                Csm[(n    ) * CSTR + m    ] = sigmoidf(acc[mt][nt][0]);
                Csm[(n + 1) * CSTR + m    ] = sigmoidf(acc[mt][nt][1]);
                Csm[(n    ) * CSTR + m + 8] = sigmoidf(acc[mt][nt][2]);
                Csm[(n + 1) * CSTR + m + 8] = sigmoidf(acc[mt][nt][3]);
            }
        }
    }
    __syncthreads();

    // write g_xsigT: 64 f-rows x 16 float4
    #pragma unroll
    for (int i = 0; i < 8; i++) {
        int idx = tid + i * 128;        // 0..1023
        int f = idx >> 4;
        int q = idx & 15;
        float4 v = *(float4*)&Csm[f * CSTR + q * 4];
        *(float4*)&g_xsigT[(size_t)(f0 + f) * BB + b0 + q * 4] = v;
    }

    // Sx partials: threads 0..63 sum their b-column over this CTA's 64 f's
    if (tid < 64) {
        float s = 0.f;
        #pragma unroll 16
        for (int f = 0; f < 64; f++) s += Csm[f * CSTR + tid];
        g_SxP[blockIdx.y * BB + b0 + tid] = s;
    }
}

// ---------------------------------------------------------------------------
// Kernel C: Tversky core.
// I[b,p] = sum_f min(xs, ps);  out = I / (I + a*(Sx-I) + b*(Sp-I) + eps) + bias
// 64(b) x 64(p) tile, 256 threads, 4x4 per thread.  grid (32, 4).
// ---------------------------------------------------------------------------
__global__ void tversky_kernel(const float* __restrict__ bias,
                               const float* __restrict__ alphap,
                               const float* __restrict__ betap,
                               float* __restrict__ out) {
    __shared__ float xs[32][64];   // [f][b]
    __shared__ float ps[32][64];   // [f][p]

    const int tid = threadIdx.x;
    const int tx = tid & 15;       // p direction (x4)
    const int ty = tid >> 4;       // b direction (x4)
    const int b0 = blockIdx.x * 64;
    const int p0 = blockIdx.y * 64;

    float acc[4][4] = {};

    for (int f0 = 0; f0 < NF; f0 += 32) {
        #pragma unroll
        for (int i = 0; i < 2; i++) {
            int idx = tid + i * 256;
            int fr  = idx >> 4;
            int bc  = (idx & 15) * 4;
            *(float4*)&xs[fr][bc] = *(const float4*)&g_xsigT[(size_t)(f0 + fr) * BB + b0 + bc];
            *(float4*)&ps[fr][bc] = *(const float4*)&g_psigT[(size_t)(f0 + fr) * NP + p0 + bc];
        }
        __syncthreads();

        #pragma unroll 8
        for (int k = 0; k < 32; k++) {
            float4 a = *(const float4*)&xs[k][ty * 4];
            float4 p = *(const float4*)&ps[k][tx * 4];
            float av[4] = {a.x, a.y, a.z, a.w};
            float pv[4] = {p.x, p.y, p.z, p.w};
            #pragma unroll
            for (int i = 0; i < 4; i++)
                #pragma unroll
                for (int j = 0; j < 4; j++)
                    acc[i][j] += fminf(av[i], pv[j]);
        }
        __syncthreads();
    }

    const float alpha = *alphap;
    const float beta  = *betap;

    float bi[4], spv[4];
    #pragma unroll
    for (int j = 0; j < 4; j++) {
        int p = p0 + tx * 4 + j;
        bi[j]  = bias[p];
        spv[j] = g_SpP[p] + g_SpP[NP + p];
    }

    #pragma unroll
    for (int i = 0; i < 4; i++) {
        int b = b0 + ty * 4 + i;
        float Sx = g_SxP[b] + g_SxP[BB + b] + g_SxP[2 * BB + b] + g_SxP[3 * BB + b];
        float4 o;
        float r[4];
        #pragma unroll
        for (int j = 0; j < 4; j++) {
            float I = acc[i][j];
            float denom = I + alpha * (Sx - I) + beta * (spv[j] - I) + EPS;
            r[j] = I / denom + bi[j];
        }
        o.x = r[0]; o.y = r[1]; o.z = r[2]; o.w = r[3];
        *(float4*)&out[(size_t)b * NP + p0 + tx * 4] = o;
    }
}

// ---------------------------------------------------------------------------
// Launch. Inputs: x, features, prototypes, bias, alpha, beta.
// ---------------------------------------------------------------------------
extern "C" void kernel_launch(void* const* d_in, const int* in_sizes, int n_in,
                              void* d_out, int out_size) {
    const float* x          = (const float*)d_in[0];
    const float* features   = (const float*)d_in[1];
    const float* prototypes = (const float*)d_in[2];
    const float* bias       = (const float*)d_in[3];
    const float* alpha      = (const float*)d_in[4];
    const float* beta       = (const float*)d_in[5];
    float* out = (float*)d_out;

    proto_sig_kernel<<<dim3(8, 2), dim3(32, 8)>>>(prototypes);
    feat_gemm_kernel<<<dim3(BB / 64, NF / 64), 128>>>(x, features);
    tversky_kernel<<<dim3(BB / 64, NP / 64), 256>>>(bias, alpha, beta, out);
}